// round 14
// baseline (speedup 1.0000x reference)
#include <cuda_runtime.h>

// SparseDownSample: 2x2 max-pool keyed on depth (first-max tie-break),
// gather winning position from depth (1ch) and geo (16ch).
// depth: [B,1,H,W] f32, geo: [B,C,H,W] f32
// out  : depth_fold [B,1,H/2,W/2] followed by geo_fold [B,C,H/2,W/2]
//
// R14 = champion (39.9-40.9us kernel, 4x reproduced) with ONE change:
// stores use __stwt (write-through) instead of __stcs, to avoid holding
// dirty write lines in L2 that compete with the read stream. Writes are
// warp-coalesced full-line (8B/lane dense), so WT sector penalty is nil.

constexpr int B  = 8;
constexpr int C  = 16;
constexpr int H  = 352;
constexpr int W  = 1216;
constexpr int H2 = H / 2;    // 176
constexpr int W2 = W / 2;    // 608
constexpr int WP = W2 / 2;   // 304 output-pixel PAIRS per row
constexpr int DEPTH_OUT_ELEMS = B * H2 * W2;  // 856064
constexpr int CB = 8;        // channels per load batch (16 float4 live)

__global__ __launch_bounds__(256)
void sds_kernel(const float* __restrict__ depth,
                const float* __restrict__ geo,
                float* __restrict__ out)
{
    const int t = blockIdx.x * blockDim.x + threadIdx.x;
    const int total = B * H2 * WP;   // 428032
    if (t >= total) return;

    const int xp   = t % WP;         // which float4 within the row
    const int rest = t / WP;
    const int y    = rest % H2;
    const int b    = rest / H2;

    // ============ opening burst: depth (2) + geo batch 0 (16) ============
    const float* drow = depth + (size_t)(b * H + 2 * y) * W;
    const float4 d0 = __ldg(reinterpret_cast<const float4*>(drow) + xp);
    const float4 d1 = __ldg(reinterpret_cast<const float4*>(drow + W) + xp);

    const float* grow = geo + ((size_t)b * C * H + 2 * y) * W;   // ch 0, row 2y
    float4 g0[CB], g1[CB];
    #pragma unroll
    for (int j = 0; j < CB; ++j) {
        const float* r0 = grow + (size_t)j * (H * W);
        g0[j] = __ldcs(reinterpret_cast<const float4*>(r0) + xp);
        g1[j] = __ldcs(reinterpret_cast<const float4*>(r0 + W) + xp);
    }

    // ---- argmax, first-max wins (strict > keeps lowest index), order:
    // 0=(r0,c0) 1=(r0,c1) 2=(r1,c0) 3=(r1,c1) -- matches unfold kh,kw order
    int   i0 = 0; float v0 = d0.x;
    if (d0.y > v0) { v0 = d0.y; i0 = 1; }
    if (d1.x > v0) { v0 = d1.x; i0 = 2; }
    if (d1.y > v0) { v0 = d1.y; i0 = 3; }

    int   i1 = 0; float v1 = d0.z;
    if (d0.w > v1) { v1 = d0.w; i1 = 1; }
    if (d1.z > v1) { v1 = d1.z; i1 = 2; }
    if (d1.w > v1) { v1 = d1.w; i1 = 3; }

    const size_t dpix = (size_t)(b * H2 + y) * W2 + (size_t)xp * 2;
    __stwt(reinterpret_cast<float2*>(out) + dpix / 2, make_float2(v0, v1));

    float* gout = out + DEPTH_OUT_ELEMS;
    const size_t obase = ((size_t)(b * C) * H2 + y) * W2 + (size_t)xp * 2;

    // ---- select + store batch 0 ----
    #pragma unroll
    for (int j = 0; j < CB; ++j) {
        const float s0 = (i0 == 0) ? g0[j].x : (i0 == 1) ? g0[j].y
                       : (i0 == 2) ? g1[j].x : g1[j].y;
        const float s1 = (i1 == 0) ? g0[j].z : (i1 == 1) ? g0[j].w
                       : (i1 == 2) ? g1[j].z : g1[j].w;
        const size_t o = obase + (size_t)j * (H2 * W2);
        __stwt(reinterpret_cast<float2*>(gout) + o / 2, make_float2(s0, s1));
    }

    // ---- batch 1: load burst, then select + store ----
    #pragma unroll
    for (int j = 0; j < CB; ++j) {
        const float* r0 = grow + (size_t)(CB + j) * (H * W);
        g0[j] = __ldcs(reinterpret_cast<const float4*>(r0) + xp);
        g1[j] = __ldcs(reinterpret_cast<const float4*>(r0 + W) + xp);
    }
    #pragma unroll
    for (int j = 0; j < CB; ++j) {
        const float s0 = (i0 == 0) ? g0[j].x : (i0 == 1) ? g0[j].y
                       : (i0 == 2) ? g1[j].x : g1[j].y;
        const float s1 = (i1 == 0) ? g0[j].z : (i1 == 1) ? g0[j].w
                       : (i1 == 2) ? g1[j].z : g1[j].w;
        const size_t o = obase + (size_t)(CB + j) * (H2 * W2);
        __stwt(reinterpret_cast<float2*>(gout) + o / 2, make_float2(s0, s1));
    }
}

extern "C" void kernel_launch(void* const* d_in, const int* in_sizes, int n_in,
                              void* d_out, int out_size)
{
    const float* depth = (const float*)d_in[0];
    const float* geo   = (const float*)d_in[1];
    float* out = (float*)d_out;

    const int total   = B * H2 * WP;          // 428032 threads
    const int threads = 256;
    const int blocks  = (total + threads - 1) / threads;
    sds_kernel<<<blocks, threads>>>(depth, geo, out);
}

// round 15
// speedup vs baseline: 1.0491x; 1.0491x over previous
#include <cuda_runtime.h>

// SparseDownSample: 2x2 max-pool keyed on depth (first-max tie-break),
// gather winning position from depth (1ch) and geo (16ch).
// depth: [B,1,H,W] f32, geo: [B,C,H,W] f32
// out  : depth_fold [B,1,H/2,W/2] followed by geo_fold [B,C,H/2,W/2]
//
// FINAL champion (4x reproduced: kernel 39.9-40.9us, bench 41.3-43.0us):
// 2 output px/thread, lane-dense float4 loads, CB=8 staged load batches
// (16 front-batched LDG.128), __ldcs geo / __stcs stores (evict-first).
// R14 showed __stwt regresses the timed loop (45.1us) despite a good
// single-launch ncu time -> writeback via L2 is the right steady-state policy.
// Sits at ~97% of the byte-traffic roofline (233MB R + 58MB W @ ~6.1TB/s).

constexpr int B  = 8;
constexpr int C  = 16;
constexpr int H  = 352;
constexpr int W  = 1216;
constexpr int H2 = H / 2;    // 176
constexpr int W2 = W / 2;    // 608
constexpr int WP = W2 / 2;   // 304 output-pixel PAIRS per row
constexpr int DEPTH_OUT_ELEMS = B * H2 * W2;  // 856064
constexpr int CB = 8;        // channels per load batch (16 float4 live)

__global__ __launch_bounds__(256)
void sds_kernel(const float* __restrict__ depth,
                const float* __restrict__ geo,
                float* __restrict__ out)
{
    const int t = blockIdx.x * blockDim.x + threadIdx.x;
    const int total = B * H2 * WP;   // 428032
    if (t >= total) return;

    const int xp   = t % WP;         // which float4 within the row
    const int rest = t / WP;
    const int y    = rest % H2;
    const int b    = rest / H2;

    // ============ opening burst: depth (2) + geo batch 0 (16) ============
    const float* drow = depth + (size_t)(b * H + 2 * y) * W;
    const float4 d0 = __ldg(reinterpret_cast<const float4*>(drow) + xp);
    const float4 d1 = __ldg(reinterpret_cast<const float4*>(drow + W) + xp);

    const float* grow = geo + ((size_t)b * C * H + 2 * y) * W;   // ch 0, row 2y
    float4 g0[CB], g1[CB];
    #pragma unroll
    for (int j = 0; j < CB; ++j) {
        const float* r0 = grow + (size_t)j * (H * W);
        g0[j] = __ldcs(reinterpret_cast<const float4*>(r0) + xp);
        g1[j] = __ldcs(reinterpret_cast<const float4*>(r0 + W) + xp);
    }

    // ---- argmax, first-max wins (strict > keeps lowest index), order:
    // 0=(r0,c0) 1=(r0,c1) 2=(r1,c0) 3=(r1,c1) -- matches unfold kh,kw order
    int   i0 = 0; float v0 = d0.x;
    if (d0.y > v0) { v0 = d0.y; i0 = 1; }
    if (d1.x > v0) { v0 = d1.x; i0 = 2; }
    if (d1.y > v0) { v0 = d1.y; i0 = 3; }

    int   i1 = 0; float v1 = d0.z;
    if (d0.w > v1) { v1 = d0.w; i1 = 1; }
    if (d1.z > v1) { v1 = d1.z; i1 = 2; }
    if (d1.w > v1) { v1 = d1.w; i1 = 3; }

    const size_t dpix = (size_t)(b * H2 + y) * W2 + (size_t)xp * 2;
    __stcs(reinterpret_cast<float2*>(out) + dpix / 2, make_float2(v0, v1));

    float* gout = out + DEPTH_OUT_ELEMS;
    const size_t obase = ((size_t)(b * C) * H2 + y) * W2 + (size_t)xp * 2;

    // ---- select + store batch 0 ----
    #pragma unroll
    for (int j = 0; j < CB; ++j) {
        const float s0 = (i0 == 0) ? g0[j].x : (i0 == 1) ? g0[j].y
                       : (i0 == 2) ? g1[j].x : g1[j].y;
        const float s1 = (i1 == 0) ? g0[j].z : (i1 == 1) ? g0[j].w
                       : (i1 == 2) ? g1[j].z : g1[j].w;
        const size_t o = obase + (size_t)j * (H2 * W2);
        __stcs(reinterpret_cast<float2*>(gout) + o / 2, make_float2(s0, s1));
    }

    // ---- batch 1: load burst, then select + store ----
    #pragma unroll
    for (int j = 0; j < CB; ++j) {
        const float* r0 = grow + (size_t)(CB + j) * (H * W);
        g0[j] = __ldcs(reinterpret_cast<const float4*>(r0) + xp);
        g1[j] = __ldcs(reinterpret_cast<const float4*>(r0 + W) + xp);
    }
    #pragma unroll
    for (int j = 0; j < CB; ++j) {
        const float s0 = (i0 == 0) ? g0[j].x : (i0 == 1) ? g0[j].y
                       : (i0 == 2) ? g1[j].x : g1[j].y;
        const float s1 = (i1 == 0) ? g0[j].z : (i1 == 1) ? g0[j].w
                       : (i1 == 2) ? g1[j].z : g1[j].w;
        const size_t o = obase + (size_t)(CB + j) * (H2 * W2);
        __stcs(reinterpret_cast<float2*>(gout) + o / 2, make_float2(s0, s1));
    }
}

extern "C" void kernel_launch(void* const* d_in, const int* in_sizes, int n_in,
                              void* d_out, int out_size)
{
    const float* depth = (const float*)d_in[0];
    const float* geo   = (const float*)d_in[1];
    float* out = (float*)d_out;

    const int total   = B * H2 * WP;          // 428032 threads
    const int threads = 256;
    const int blocks  = (total + threads - 1) / threads;
    sds_kernel<<<blocks, threads>>>(depth, geo, out);
}

// round 16
// speedup vs baseline: 1.0805x; 1.0299x over previous
#include <cuda_runtime.h>

// SparseDownSample: 2x2 max-pool keyed on depth (first-max tie-break),
// gather winning position from depth (1ch) and geo (16ch).
// depth: [B,1,H,W] f32, geo: [B,C,H,W] f32
// out  : depth_fold [B,1,H/2,W/2] followed by geo_fold [B,C,H/2,W/2]
//
// FINAL champion (5x reproduced: kernel 39.9-40.9us, bench 41.3-43.0us):
// 2 output px/thread, lane-dense float4 loads, CB=8 staged load batches
// (16 front-batched LDG.128), __ldcs geo / __stcs stores (evict-first).
// Measured >=97% of the byte-traffic roofline (233MB R + 58MB W at the
// ~6.1TB/s achieved mixed R/W DRAM ceiling on this part). All explored
// deviations (CB=4/16/34, wide tiles, persistent grid, __stwt) regressed.

constexpr int B  = 8;
constexpr int C  = 16;
constexpr int H  = 352;
constexpr int W  = 1216;
constexpr int H2 = H / 2;    // 176
constexpr int W2 = W / 2;    // 608
constexpr int WP = W2 / 2;   // 304 output-pixel PAIRS per row
constexpr int DEPTH_OUT_ELEMS = B * H2 * W2;  // 856064
constexpr int CB = 8;        // channels per load batch (16 float4 live)

__global__ __launch_bounds__(256)
void sds_kernel(const float* __restrict__ depth,
                const float* __restrict__ geo,
                float* __restrict__ out)
{
    const int t = blockIdx.x * blockDim.x + threadIdx.x;
    const int total = B * H2 * WP;   // 428032
    if (t >= total) return;

    const int xp   = t % WP;         // which float4 within the row
    const int rest = t / WP;
    const int y    = rest % H2;
    const int b    = rest / H2;

    // ============ opening burst: depth (2) + geo batch 0 (16) ============
    const float* drow = depth + (size_t)(b * H + 2 * y) * W;
    const float4 d0 = __ldg(reinterpret_cast<const float4*>(drow) + xp);
    const float4 d1 = __ldg(reinterpret_cast<const float4*>(drow + W) + xp);

    const float* grow = geo + ((size_t)b * C * H + 2 * y) * W;   // ch 0, row 2y
    float4 g0[CB], g1[CB];
    #pragma unroll
    for (int j = 0; j < CB; ++j) {
        const float* r0 = grow + (size_t)j * (H * W);
        g0[j] = __ldcs(reinterpret_cast<const float4*>(r0) + xp);
        g1[j] = __ldcs(reinterpret_cast<const float4*>(r0 + W) + xp);
    }

    // ---- argmax, first-max wins (strict > keeps lowest index), order:
    // 0=(r0,c0) 1=(r0,c1) 2=(r1,c0) 3=(r1,c1) -- matches unfold kh,kw order
    int   i0 = 0; float v0 = d0.x;
    if (d0.y > v0) { v0 = d0.y; i0 = 1; }
    if (d1.x > v0) { v0 = d1.x; i0 = 2; }
    if (d1.y > v0) { v0 = d1.y; i0 = 3; }

    int   i1 = 0; float v1 = d0.z;
    if (d0.w > v1) { v1 = d0.w; i1 = 1; }
    if (d1.z > v1) { v1 = d1.z; i1 = 2; }
    if (d1.w > v1) { v1 = d1.w; i1 = 3; }

    const size_t dpix = (size_t)(b * H2 + y) * W2 + (size_t)xp * 2;
    __stcs(reinterpret_cast<float2*>(out) + dpix / 2, make_float2(v0, v1));

    float* gout = out + DEPTH_OUT_ELEMS;
    const size_t obase = ((size_t)(b * C) * H2 + y) * W2 + (size_t)xp * 2;

    // ---- select + store batch 0 ----
    #pragma unroll
    for (int j = 0; j < CB; ++j) {
        const float s0 = (i0 == 0) ? g0[j].x : (i0 == 1) ? g0[j].y
                       : (i0 == 2) ? g1[j].x : g1[j].y;
        const float s1 = (i1 == 0) ? g0[j].z : (i1 == 1) ? g0[j].w
                       : (i1 == 2) ? g1[j].z : g1[j].w;
        const size_t o = obase + (size_t)j * (H2 * W2);
        __stcs(reinterpret_cast<float2*>(gout) + o / 2, make_float2(s0, s1));
    }

    // ---- batch 1: load burst, then select + store ----
    #pragma unroll
    for (int j = 0; j < CB; ++j) {
        const float* r0 = grow + (size_t)(CB + j) * (H * W);
        g0[j] = __ldcs(reinterpret_cast<const float4*>(r0) + xp);
        g1[j] = __ldcs(reinterpret_cast<const float4*>(r0 + W) + xp);
    }
    #pragma unroll
    for (int j = 0; j < CB; ++j) {
        const float s0 = (i0 == 0) ? g0[j].x : (i0 == 1) ? g0[j].y
                       : (i0 == 2) ? g1[j].x : g1[j].y;
        const float s1 = (i1 == 0) ? g0[j].z : (i1 == 1) ? g0[j].w
                       : (i1 == 2) ? g1[j].z : g1[j].w;
        const size_t o = obase + (size_t)(CB + j) * (H2 * W2);
        __stcs(reinterpret_cast<float2*>(gout) + o / 2, make_float2(s0, s1));
    }
}

extern "C" void kernel_launch(void* const* d_in, const int* in_sizes, int n_in,
                              void* d_out, int out_size)
{
    const float* depth = (const float*)d_in[0];
    const float* geo   = (const float*)d_in[1];
    float* out = (float*)d_out;

    const int total   = B * H2 * WP;          // 428032 threads
    const int threads = 256;
    const int blocks  = (total + threads - 1) / threads;
    sds_kernel<<<blocks, threads>>>(depth, geo, out);
}